// round 11
// baseline (speedup 1.0000x reference)
#include <cuda_runtime.h>
#include <cstdint>
#include <cstddef>

#define NROWS   65536
#define NCLS    1000
#define DFEAT   256
#define MROWS   64
#define NCTA    (NROWS / MROWS)      /* 1024 */
#define KSTEPS  32
#define THREADS 256
/* B stage: MMA section 1152 u32 (2 wn x [4 pairs x 128 + 64]) + DP 896 (112 dims x 8) */
#define MMA_U32 1152
#define STG_U32 2048
#define NSTG    4
#define RAWSTR  36                    /* raw gt tile row stride, u32 */
#define RAW_U32 (64 * RAWSTR)         /* 2304 per stage */
#define ROWTSTR 12

/* smem offsets in u32 */
#define OFF_B    0
#define OFF_RAW  (NSTG * STG_U32)                 /* 8192  */
#define OFF_FRAG (OFF_RAW + NSTG * RAW_U32)       /* 17408 */
#define OFF_ROWT (OFF_FRAG + 512)                 /* 17920 */
#define OFF_CSQ  (OFF_ROWT + 768)                 /* 18688 */
#define OFF_CNT  (OFF_CSQ + 512)                  /* 19200 */
#define OFF_RED  (OFF_CNT + 64)                   /* 19264 */
#define SMEM_U32 (OFF_RED + 8)                    /* 19272 -> 77088 B */

// ---------------- device scratch ----------------
__device__ __align__(16) uint32_t g_B[KSTEPS * STG_U32];  // 256 KB
__device__ float     g_csqf[1024];
__device__ __align__(8) uint32_t g_csqpk[512];
__device__ float     g_partial[NCTA];

// ---------------- ptx helpers ----------------
__device__ __forceinline__ uint32_t smem_u32(const void* p) {
    uint32_t a;
    asm("{ .reg .u64 t; cvta.to.shared.u64 t, %1; cvt.u32.u64 %0, t; }" : "=r"(a) : "l"(p));
    return a;
}
__device__ __forceinline__ void cp_async16(uint32_t dst, const void* src) {
    asm volatile("cp.async.cg.shared.global [%0], [%1], 16;" :: "r"(dst), "l"(src));
}
__device__ __forceinline__ void cp_async16z(uint32_t dst, const void* src, uint32_t nbytes) {
    asm volatile("cp.async.cg.shared.global [%0], [%1], 16, %2;"
                 :: "r"(dst), "l"(src), "r"(nbytes));
}
__device__ __forceinline__ void cp_commit() { asm volatile("cp.async.commit_group;" ::: "memory"); }
__device__ __forceinline__ void cp_wait2()  { asm volatile("cp.async.wait_group 2;" ::: "memory"); }

__device__ __forceinline__ int dp4a(uint32_t a, uint32_t b, int c) {
    int r;
    asm("dp4a.s32.s32 %0, %1, %2, %3;" : "=r"(r) : "r"(a), "r"(b), "r"(c));
    return r;
}
__device__ __forceinline__ uint32_t pack01(int4 v) {
    uint32_t t0, t1, r;
    asm("prmt.b32 %0, %1, %2, 0x0040;" : "=r"(t0) : "r"((uint32_t)v.x), "r"((uint32_t)v.y));
    asm("prmt.b32 %0, %1, %2, 0x0040;" : "=r"(t1) : "r"((uint32_t)v.z), "r"((uint32_t)v.w));
    asm("prmt.b32 %0, %1, %2, 0x5410;" : "=r"(r)  : "r"(t0), "r"(t1));
    return r;
}
__device__ __forceinline__ void mma_s8(int* c, uint32_t a0, uint32_t a1, uint32_t a2, uint32_t a3,
                                       uint32_t b0, uint32_t b1) {
    asm volatile(
        "mma.sync.aligned.m16n8k32.row.col.s32.s8.s8.s32 "
        "{%0,%1,%2,%3}, {%4,%5,%6,%7}, {%8,%9}, {%0,%1,%2,%3};"
        : "+r"(c[0]), "+r"(c[1]), "+r"(c[2]), "+r"(c[3])
        : "r"(a0), "r"(a1), "r"(a2), "r"(a3), "r"(b0), "r"(b1));
}

// ================= prep kernels =================
__global__ void prep_csq(const float* __restrict__ cen) {
    int w = threadIdx.x >> 5, l = threadIdx.x & 31;
    int c = blockIdx.x * 8 + w;
    float s = 0.f;
    #pragma unroll
    for (int j = 0; j < 8; j++) { float v = cen[(size_t)c * DFEAT + l + j * 32]; s += v * v; }
    #pragma unroll
    for (int o = 16; o; o >>= 1) s += __shfl_xor_sync(0xffffffffu, s, o);
    if (l == 0) g_csqf[c] = s;
}

// B layout per step s (2048 u32):
//  MMA [0,1152): wn half 576 u32: pairs p<4: q=wn*576+p*128+lane*4+{li-lo r0,r1, li-hi r0,r1};
//                single li=8 at +512 + lane*2 + r.  dim=(wn*9+li)*8+(lane>>2); c0=s*32+(lane&3)*4+r*16
//  DP  [1152,2048): dim-major: (dd<112)*8 + kw; dim=144+dd; c0=s*32+kw*4
__global__ void prep_b(const float* __restrict__ cen) {
    int e = blockIdx.x * 256 + threadIdx.x;      // 0..65535
    int s = e >> 11, q = e & 2047;
    int dim, c0;
    if (q < MMA_U32) {
        int wn = q / 576, q2 = q - wn * 576;
        int li, lane, r;
        if (q2 < 512) {
            int p = q2 >> 7; lane = (q2 >> 2) & 31; int w4 = q2 & 3;
            li = 2 * p + (w4 >> 1); r = w4 & 1;
        } else {
            li = 8; lane = (q2 - 512) >> 1; r = q2 & 1;
        }
        dim = (wn * 9 + li) * 8 + (lane >> 2);
        c0  = s * 32 + (lane & 3) * 4 + r * 16;
    } else {
        int q2 = q - MMA_U32;
        dim = 144 + (q2 >> 3);
        c0  = s * 32 + (q2 & 7) * 4;
    }
    uint32_t packed = 0;
    #pragma unroll
    for (int j = 0; j < 4; j++) {
        int c = c0 + j;
        int v = 0;
        if (c < NCLS) v = __float2int_rn(16.0f * cen[(size_t)c * DFEAT + dim]);
        packed |= (uint32_t)(v & 0xFF) << (8 * j);
    }
    g_B[e] = packed;

    if (blockIdx.x == 0) {
        int qq = threadIdx.x;
        uint32_t hi = 0, lo = 0;
        #pragma unroll
        for (int j = 0; j < 4; j++) {
            int c   = qq * 4 + j;
            int q16 = (c < NCLS) ? (int)rintf(64.0f * g_csqf[c]) : 0;
            int h   = q16 >> 8;
            int l8  = (q16 & 255) - 128;
            hi |= (uint32_t)(h  & 0xFF) << (8 * j);
            lo |= (uint32_t)(l8 & 0xFF) << (8 * j);
        }
        g_csqpk[qq * 2]     = hi;
        g_csqpk[qq * 2 + 1] = lo;
    }
}

__global__ void init_partials() {
    int i = blockIdx.x * 256 + threadIdx.x;
    if (i < NCTA) g_partial[i] = 0.f;
}

// ================= main kernel: 256 threads, 2 CTAs/SM =================
__global__ void __launch_bounds__(THREADS, 2)
center_main(const int* __restrict__ gt, const float* __restrict__ feat) {
    extern __shared__ __align__(16) uint32_t sm[];
    int*   sCnt = (int*)(sm + OFF_CNT);
    float* sRed = (float*)(sm + OFF_RED);

    const int tid  = threadIdx.x, wid = tid >> 5, lane = tid & 31;
    const int wm   = wid & 3, wn = wid >> 2;
    const int gq   = lane >> 2, tig = lane & 3;
    const int rl   = wm * 16 + gq;
    const size_t rowbase = (size_t)blockIdx.x * MROWS;

    sm[OFF_CSQ + tid]       = g_csqpk[tid];
    sm[OFF_CSQ + 256 + tid] = g_csqpk[256 + tid];
    if (tid < 64) sCnt[tid] = 0;

    const uint32_t smb = smem_u32(sm);

    // prefetch stages 0..2 (B + raw gt)
    #pragma unroll
    for (int s = 0; s < 3; s++) {
        #pragma unroll
        for (int j = 0; j < 2; j++) {
            int i = tid + j * 256;
            cp_async16(smb + (uint32_t)(OFF_B + s * STG_U32 + i * 4) * 4,
                       (const void*)(g_B + (size_t)s * STG_U32 + i * 4));
        }
        #pragma unroll
        for (int j = 0; j < 2; j++) {
            int c = tid + j * 256;                   // 0..511
            int row = c >> 3, part = c & 7;
            int cb = s * 32 + part * 4;
            cp_async16z(smb + (uint32_t)(OFF_RAW + s * RAW_U32 + row * RAWSTR + part * 4) * 4,
                        (const void*)(gt + (rowbase + row) * NCLS + cb),
                        (cb + 4 <= NCLS) ? 16u : 0u);
        }
        cp_commit();
    }

    int acc[9][4];
    #pragma unroll
    for (int i = 0; i < 9; i++) { acc[i][0] = acc[i][1] = acc[i][2] = acc[i][3] = 0; }
    int pacc[28];
    #pragma unroll
    for (int j = 0; j < 28; j++) pacc[j] = 0;
    int cntA = 0, cntB = 0, accHi = 0, accLo = 0;

    // pack-task constants for this thread
    const int fu  = tid * 2;
    const int pj  = fu & 3;                  // 0 or 2
    const int plf = (fu >> 2) & 31;
    const int pwm = fu >> 7;
    const int prow = pwm * 16 + (plf >> 2);
    const int pkw  = (plf & 3) + (pj >> 1) * 4;

    for (int s = 0; s < KSTEPS; s++) {
        const int slot = s & 3;
        cp_wait2();
        __syncthreads();

        // ---- pack raw gt (int32) -> byte tiles ----
        {
            const uint32_t* rawp = sm + OFF_RAW + slot * RAW_U32;
            int4 v0 = *(const int4*)(rawp + prow * RAWSTR + pkw * 4);
            int4 v1 = *(const int4*)(rawp + (prow + 8) * RAWSTR + pkw * 4);
            uint32_t p0 = pack01(v0), p1 = pack01(v1);
            *(uint2*)(sm + OFF_FRAG + fu) = make_uint2(p0, p1);
            sm[OFF_ROWT + prow * ROWTSTR + pkw]       = p0;
            sm[OFF_ROWT + (prow + 8) * ROWTSTR + pkw] = p1;
        }

        // ---- prefetch stage s+3 ----
        if (s + 3 < KSTEPS) {
            const int fs = s + 3, fslot = fs & 3;
            #pragma unroll
            for (int j = 0; j < 2; j++) {
                int i = tid + j * 256;
                cp_async16(smb + (uint32_t)(OFF_B + fslot * STG_U32 + i * 4) * 4,
                           (const void*)(g_B + (size_t)fs * STG_U32 + i * 4));
            }
            #pragma unroll
            for (int j = 0; j < 2; j++) {
                int c = tid + j * 256;
                int row = c >> 3, part = c & 7;
                int cb = fs * 32 + part * 4;
                cp_async16z(smb + (uint32_t)(OFF_RAW + fslot * RAW_U32 + row * RAWSTR + part * 4) * 4,
                            (const void*)(gt + (rowbase + row) * NCLS + cb),
                            (cb + 4 <= NCLS) ? 16u : 0u);
            }
        }
        cp_commit();
        __syncthreads();

        // ---- A fragment (1 LDS.128) ----
        uint4 Af = *(const uint4*)(sm + OFF_FRAG + (wm * 32 + lane) * 4);
        uint32_t A0 = Af.x, A1 = Af.y, A2 = Af.z, A3 = Af.w;

        // ---- side term ----
        uint2 cqa = *(const uint2*)(sm + OFF_CSQ + (s * 8 + tig) * 2);
        uint2 cqb = *(const uint2*)(sm + OFF_CSQ + (s * 8 + tig + 4) * 2);
        cntA  = dp4a(A0, 0x01010101u, cntA);  cntA  = dp4a(A2, 0x01010101u, cntA);
        cntB  = dp4a(A1, 0x01010101u, cntB);  cntB  = dp4a(A3, 0x01010101u, cntB);
        accHi = dp4a(A0, cqa.x, accHi);       accHi = dp4a(A1, cqa.x, accHi);
        accHi = dp4a(A2, cqb.x, accHi);       accHi = dp4a(A3, cqb.x, accHi);
        accLo = dp4a(A0, cqa.y, accLo);       accLo = dp4a(A1, cqa.y, accLo);
        accLo = dp4a(A2, cqb.y, accLo);       accLo = dp4a(A3, cqb.y, accLo);

        // ---- tensor path: 9 MMAs (4 paired loads + 1) ----
        const uint32_t* bp = sm + OFF_B + slot * STG_U32 + wn * 576;
        #pragma unroll
        for (int p = 0; p < 4; p++) {
            uint4 bb = *(const uint4*)(bp + p * 128 + lane * 4);
            mma_s8(acc[2 * p],     A0, A1, A2, A3, bb.x, bb.y);
            mma_s8(acc[2 * p + 1], A0, A1, A2, A3, bb.z, bb.w);
        }
        {
            uint2 b8 = *(const uint2*)(bp + 512 + lane * 2);
            mma_s8(acc[8], A0, A1, A2, A3, b8.x, b8.y);
        }

        // ---- dp4a path: rows (lane, lane+32), dims 144+wid*14..+14 ----
        {
            const uint32_t* dpB = sm + OFF_B + slot * STG_U32 + MMA_U32 + wid * 112;
            const uint32_t* mr0 = sm + OFF_ROWT + lane * ROWTSTR;
            const uint32_t* mr1 = mr0 + 32 * ROWTSTR;
            uint4 m0a = *(const uint4*)(mr0), m0b = *(const uint4*)(mr0 + 4);
            uint4 m1a = *(const uint4*)(mr1), m1b = *(const uint4*)(mr1 + 4);
            #pragma unroll
            for (int d = 0; d < 14; d++) {
                uint4 b0 = *(const uint4*)(dpB + d * 8);
                uint4 b1 = *(const uint4*)(dpB + d * 8 + 4);
                int a0 = pacc[d * 2], a1 = pacc[d * 2 + 1];
                a0 = dp4a(m0a.x, b0.x, a0); a0 = dp4a(m0a.y, b0.y, a0);
                a0 = dp4a(m0a.z, b0.z, a0); a0 = dp4a(m0a.w, b0.w, a0);
                a0 = dp4a(m0b.x, b1.x, a0); a0 = dp4a(m0b.y, b1.y, a0);
                a0 = dp4a(m0b.z, b1.z, a0); a0 = dp4a(m0b.w, b1.w, a0);
                a1 = dp4a(m1a.x, b0.x, a1); a1 = dp4a(m1a.y, b0.y, a1);
                a1 = dp4a(m1a.z, b0.z, a1); a1 = dp4a(m1a.w, b0.w, a1);
                a1 = dp4a(m1b.x, b1.x, a1); a1 = dp4a(m1b.y, b1.y, a1);
                a1 = dp4a(m1b.z, b1.z, a1); a1 = dp4a(m1b.w, b1.w, a1);
                pacc[d * 2] = a0; pacc[d * 2 + 1] = a1;
            }
        }
    }

    // ---- epilogue ----
    atomicAdd(&sCnt[rl],     cntA);
    atomicAdd(&sCnt[rl + 8], cntB);
    __syncthreads();

    // tensor side: rows rl, rl+8; dims wn*72 .. +72
    const float* f0 = feat + (rowbase + rl) * DFEAT + wn * 72 + tig * 2;
    const float* f1 = f0 + (size_t)8 * DFEAT;
    float cr = 0.f, s2a = 0.f, s2b = 0.f;
    #pragma unroll
    for (int li = 0; li < 9; li++) {
        float2 v0 = *(const float2*)(f0 + li * 8);
        float2 v1 = *(const float2*)(f1 + li * 8);
        cr  += v0.x * (float)acc[li][0] + v0.y * (float)acc[li][1]
             + v1.x * (float)acc[li][2] + v1.y * (float)acc[li][3];
        s2a += v0.x * v0.x + v0.y * v0.y;
        s2b += v1.x * v1.x + v1.y * v1.y;
    }
    int   c64i = accHi * 256 + accLo + 128 * (cntA + cntB);
    float thr = s2a * (0.5f * (float)sCnt[rl]) + s2b * (0.5f * (float)sCnt[rl + 8])
              + (float)c64i * (1.0f / 128.0f)
              - cr * 0.125f;

    // dp side: rows lane & lane+32; dims 144 + wid*14 .. +14
    #pragma unroll
    for (int h = 0; h < 2; h++) {
        int r = lane + h * 32;
        const float* fd = feat + (rowbase + r) * DFEAT + 144 + wid * 14;
        float crd = 0.f, s2d = 0.f;
        #pragma unroll
        for (int d = 0; d < 14; d++) {
            float v = fd[d];
            crd += v * (float)pacc[d * 2 + h];
            s2d += v * v;
        }
        thr += s2d * (0.5f * (float)sCnt[r]) - crd * 0.125f;
    }

    #pragma unroll
    for (int o = 16; o; o >>= 1) thr += __shfl_xor_sync(0xffffffffu, thr, o);
    if (lane == 0) sRed[wid] = thr;
    __syncthreads();
    if (tid == 0) {
        float v = 0.f;
        #pragma unroll
        for (int i = 0; i < 8; i++) v += sRed[i];
        g_partial[blockIdx.x] = v;
    }
}

__global__ void finalize_loss(float* __restrict__ out) {
    __shared__ float sr[8];
    int tid = threadIdx.x, wid = tid >> 5, lane = tid & 31;
    float v = 0.f;
    #pragma unroll
    for (int j = 0; j < 4; j++) v += g_partial[tid + j * 256];
    #pragma unroll
    for (int o = 16; o; o >>= 1) v += __shfl_xor_sync(0xffffffffu, v, o);
    if (lane == 0) sr[wid] = v;
    __syncthreads();
    if (wid == 0) {
        float t = (lane < 8) ? sr[lane] : 0.f;
        #pragma unroll
        for (int o = 4; o; o >>= 1) t += __shfl_xor_sync(0xffffffffu, t, o);
        if (lane == 0) out[0] = t * (1.0f / (float)NROWS);
    }
}

// ================= launch =================
extern "C" void kernel_launch(void* const* d_in, const int* in_sizes, int n_in,
                              void* d_out, int out_size) {
    const int*   gt   = (const int*)d_in[0];
    const float* feat = (const float*)d_in[1];
    const float* cen  = (const float*)d_in[2];
    float* out = (float*)d_out;

    cudaFuncSetAttribute(center_main, cudaFuncAttributeMaxDynamicSharedMemorySize,
                         SMEM_U32 * 4);

    prep_csq<<<125, 256>>>(cen);                           // 0
    prep_b<<<256, 256>>>(cen);                             // 1
    init_partials<<<4, 256>>>();                           // 2
    center_main<<<NCTA, THREADS, SMEM_U32 * 4>>>(gt, feat);// 3 — ncu capture slot
    finalize_loss<<<1, 256>>>(out);                        // 4
}